// round 1
// baseline (speedup 1.0000x reference)
#include <cuda_runtime.h>
#include <math.h>

// Problem constants
#define BATCH 16
#define SEQ   1024
#define EMB   768
#define HEADS 12
#define HDIM  64          // per-head dim
#define DQK   1536        // 2*D_K
#define MTOT  (BATCH*SEQ) // 16384

// ---------------- scratch (static device globals; no allocation) ----------------
__device__ float g_tmp_qk[(size_t)MTOT * DQK];   // x @ W_qk + b   [M,1536]
__device__ float g_tmp_v [(size_t)MTOT * EMB];   // x @ W_v  + b   [M,768]
__device__ float g_Q[(size_t)BATCH*HEADS*SEQ*HDIM];
__device__ float g_K[(size_t)BATCH*HEADS*SEQ*HDIM];
__device__ float g_V[(size_t)BATCH*HEADS*SEQ*HDIM];
__device__ float g_O[(size_t)MTOT * EMB];        // attention output [B,N,768]

// ---------------- generic fp32 SGEMM: C = A[MxK] @ B[KxN] + bias ----------------
#define BM 64
#define BN 64
#define BK 16

__global__ __launch_bounds__(256) void sgemm_bias(
    const float* __restrict__ A, const float* __restrict__ B,
    const float* __restrict__ bias, float* __restrict__ C,
    int M, int N, int K)
{
    __shared__ float As[BK][BM];      // A stored k-major for broadcast reads
    __shared__ float Bs[BK][BN];

    int tid = threadIdx.x;
    int tx = tid & 15;                // 16 col groups
    int ty = tid >> 4;                // 16 row groups
    int m0 = blockIdx.y * BM;
    int n0 = blockIdx.x * BN;

    float acc[4][4] = {};

    for (int k0 = 0; k0 < K; k0 += BK) {
        // load A tile 64x16 (1024 elems / 256 thr = 4 each)
        #pragma unroll
        for (int i = 0; i < 4; i++) {
            int lin = tid + i * 256;
            int r = lin >> 4, c = lin & 15;
            As[c][r] = A[(size_t)(m0 + r) * K + k0 + c];
        }
        // load B tile 16x64 (fully coalesced rows)
        #pragma unroll
        for (int i = 0; i < 4; i++) {
            int lin = tid + i * 256;
            int r = lin >> 6, c = lin & 63;
            Bs[r][c] = B[(size_t)(k0 + r) * N + n0 + c];
        }
        __syncthreads();

        #pragma unroll
        for (int k = 0; k < BK; k++) {
            float a[4], bb[4];
            #pragma unroll
            for (int i = 0; i < 4; i++) a[i]  = As[k][ty * 4 + i];
            #pragma unroll
            for (int j = 0; j < 4; j++) bb[j] = Bs[k][tx * 4 + j];
            #pragma unroll
            for (int i = 0; i < 4; i++)
                #pragma unroll
                for (int j = 0; j < 4; j++)
                    acc[i][j] += a[i] * bb[j];
        }
        __syncthreads();
    }

    #pragma unroll
    for (int i = 0; i < 4; i++) {
        int r = m0 + ty * 4 + i;
        #pragma unroll
        for (int j = 0; j < 4; j++) {
            int c = n0 + tx * 4 + j;
            C[(size_t)r * N + c] = acc[i][j] + bias[c];
        }
    }
}

// ---------------- scatter: tmp_qk/tmp_v -> Q,K,V in [B,H,N,64] ----------------
__global__ __launch_bounds__(256) void scatter_qkv()
{
    int idx = blockIdx.x * 256 + threadIdx.x;       // over B*H*N*64 = 12.58M
    if (idx >= BATCH * HEADS * SEQ * HDIM) return;
    int dd = idx & 63;
    int t  = idx >> 6;
    int n  = t & (SEQ - 1);
    t >>= 10;
    int h  = t % HEADS;
    int b  = t / HEADS;

    size_t row = (size_t)(b * SEQ + n);
    // qk last dim splits as (h, d, 2): col = h*128 + dd*2 + sel
    float q = g_tmp_qk[row * DQK + h * 128 + dd * 2 + 0];
    float k = g_tmp_qk[row * DQK + h * 128 + dd * 2 + 1];
    float v = g_tmp_v [row * EMB + h * HDIM + dd];
    g_Q[idx] = q;
    g_K[idx] = k;
    g_V[idx] = v;
}

// ---------------- flash-style attention ----------------
// grid: (SEQ/AQ, HEADS, BATCH), 256 threads (8 warps), each warp owns 2 q rows.
#define AQ 16     // q rows per CTA
#define AT 64     // kv tile size

__global__ __launch_bounds__(256) void attention_kernel()
{
    __shared__ float Qs[AQ][65];
    __shared__ float Ks[AT][65];
    __shared__ float Vs[AT][65];

    int b = blockIdx.z, h = blockIdx.y;
    int q0 = blockIdx.x * AQ;
    int tid = threadIdx.x;
    int warp = tid >> 5, lane = tid & 31;
    const float scale = 0.125f;   // 1/sqrt(64)

    const float* Qb = g_Q + ((size_t)(b * HEADS + h) * SEQ + q0) * HDIM;
    const float* Kb = g_K + ((size_t)(b * HEADS + h) * SEQ) * HDIM;
    const float* Vb = g_V + ((size_t)(b * HEADS + h) * SEQ) * HDIM;

    // load Q tile (scaled)
    for (int i = tid; i < AQ * HDIM; i += 256) {
        int r = i >> 6, c = i & 63;
        Qs[r][c] = Qb[r * HDIM + c] * scale;
    }

    int r0 = warp * 2, r1 = warp * 2 + 1;
    int c0 = lane, c1 = lane + 32;

    float m0 = -1e30f, m1 = -1e30f;
    float l0 = 0.f, l1 = 0.f;
    float acc00 = 0.f, acc01 = 0.f, acc10 = 0.f, acc11 = 0.f;

    for (int t = 0; t < SEQ; t += AT) {
        __syncthreads();   // protect smem reuse (also covers Q-store before first use)
        for (int i = tid; i < AT * HDIM; i += 256) {
            int r = i >> 6, c = i & 63;
            Ks[r][c] = Kb[(size_t)(t + r) * HDIM + c];
            Vs[r][c] = Vb[(size_t)(t + r) * HDIM + c];
        }
        __syncthreads();

        // S = Q @ K^T  (each lane: 2 rows x 2 cols)
        float s00 = 0.f, s01 = 0.f, s10 = 0.f, s11 = 0.f;
        #pragma unroll
        for (int d = 0; d < HDIM; d++) {
            float qa = Qs[r0][d], qb = Qs[r1][d];
            float ka = Ks[c0][d], kb = Ks[c1][d];
            s00 += qa * ka; s01 += qa * kb;
            s10 += qb * ka; s11 += qb * kb;
        }

        // per-row tile max (over 64 cols spread across 32 lanes x2)
        float t0 = fmaxf(s00, s01), t1 = fmaxf(s10, s11);
        #pragma unroll
        for (int o = 16; o; o >>= 1) {
            t0 = fmaxf(t0, __shfl_xor_sync(0xffffffffu, t0, o));
            t1 = fmaxf(t1, __shfl_xor_sync(0xffffffffu, t1, o));
        }
        float nm0 = fmaxf(m0, t0), nm1 = fmaxf(m1, t1);
        float p00 = __expf(s00 - nm0), p01 = __expf(s01 - nm0);
        float p10 = __expf(s10 - nm1), p11 = __expf(s11 - nm1);
        float corr0 = __expf(m0 - nm0), corr1 = __expf(m1 - nm1);
        m0 = nm0; m1 = nm1;

        float ps0 = p00 + p01, ps1 = p10 + p11;
        #pragma unroll
        for (int o = 16; o; o >>= 1) {
            ps0 += __shfl_xor_sync(0xffffffffu, ps0, o);
            ps1 += __shfl_xor_sync(0xffffffffu, ps1, o);
        }
        l0 = l0 * corr0 + ps0;
        l1 = l1 * corr1 + ps1;
        acc00 *= corr0; acc01 *= corr0;
        acc10 *= corr1; acc11 *= corr1;

        // O += P @ V : broadcast p over lanes, each lane owns 2 v-cols
        #pragma unroll
        for (int kk = 0; kk < 32; kk++) {
            float pa = __shfl_sync(0xffffffffu, p00, kk);
            float pb = __shfl_sync(0xffffffffu, p10, kk);
            float va = Vs[kk][c0], vb = Vs[kk][c1];
            acc00 += pa * va; acc01 += pa * vb;
            acc10 += pb * va; acc11 += pb * vb;
        }
        #pragma unroll
        for (int kk = 0; kk < 32; kk++) {
            float pa = __shfl_sync(0xffffffffu, p01, kk);
            float pb = __shfl_sync(0xffffffffu, p11, kk);
            float va = Vs[32 + kk][c0], vb = Vs[32 + kk][c1];
            acc00 += pa * va; acc01 += pa * vb;
            acc10 += pb * va; acc11 += pb * vb;
        }
    }

    // normalize + write O in [B, N, H*64] layout (ready for proj GEMM)
    float inv0 = 1.f / l0, inv1 = 1.f / l1;
    int n0 = q0 + r0, n1 = q0 + r1;
    float* Ob = g_O + (size_t)b * SEQ * EMB + h * HDIM;
    Ob[(size_t)n0 * EMB + lane]      = acc00 * inv0;
    Ob[(size_t)n0 * EMB + lane + 32] = acc01 * inv0;
    Ob[(size_t)n1 * EMB + lane]      = acc10 * inv1;
    Ob[(size_t)n1 * EMB + lane + 32] = acc11 * inv1;
}

// ---------------- launch ----------------
extern "C" void kernel_launch(void* const* d_in, const int* in_sizes, int n_in,
                              void* d_out, int out_size)
{
    const float* x      = (const float*)d_in[0];
    const float* W_qk   = (const float*)d_in[1];
    const float* b_qk   = (const float*)d_in[2];
    const float* W_v    = (const float*)d_in[3];
    const float* b_v    = (const float*)d_in[4];
    const float* W_proj = (const float*)d_in[5];
    const float* b_proj = (const float*)d_in[6];
    float* out = (float*)d_out;

    float *tqk, *tv, *O;
    cudaGetSymbolAddress((void**)&tqk, g_tmp_qk);
    cudaGetSymbolAddress((void**)&tv,  g_tmp_v);
    cudaGetSymbolAddress((void**)&O,   g_O);

    // 1) projections
    {
        dim3 grid(DQK / BN, MTOT / BM);
        sgemm_bias<<<grid, 256>>>(x, W_qk, b_qk, tqk, MTOT, DQK, EMB);
    }
    {
        dim3 grid(EMB / BN, MTOT / BM);
        sgemm_bias<<<grid, 256>>>(x, W_v, b_v, tv, MTOT, EMB, EMB);
    }

    // 2) scatter to head layouts
    {
        int total = BATCH * HEADS * SEQ * HDIM;
        scatter_qkv<<<(total + 255) / 256, 256>>>();
    }

    // 3) attention
    {
        dim3 grid(SEQ / AQ, HEADS, BATCH);
        attention_kernel<<<grid, 256>>>();
    }

    // 4) output projection
    {
        dim3 grid(EMB / BN, MTOT / BM);
        sgemm_bias<<<grid, 256>>>(O, W_proj, b_proj, out, MTOT, EMB, EMB);
    }
}

// round 4
// speedup vs baseline: 1.4695x; 1.4695x over previous
#include <cuda_runtime.h>
#include <cuda_bf16.h>
#include <cstdint>
#include <math.h>

// Problem constants
#define BATCH 16
#define SEQ   1024
#define EMB   768
#define HEADS 12
#define HDIM  64
#define DQK   1536
#define MTOT  (BATCH*SEQ) // 16384

// ======================= scratch =======================
__device__ float g_tmp_qk[(size_t)MTOT * DQK];
__device__ float g_tmp_v [(size_t)MTOT * EMB];
__device__ float g_Q[(size_t)BATCH*HEADS*SEQ*HDIM];
__device__ float g_K[(size_t)BATCH*HEADS*SEQ*HDIM];
__device__ float g_V[(size_t)BATCH*HEADS*SEQ*HDIM];
__device__ float g_O[(size_t)MTOT * EMB];
__device__ __nv_bfloat16 g_xhi[(size_t)MTOT*EMB], g_xlo[(size_t)MTOT*EMB];
__device__ __nv_bfloat16 g_Ohi[(size_t)MTOT*EMB], g_Olo[(size_t)MTOT*EMB];
__device__ __nv_bfloat16 g_Wqkhi[(size_t)DQK*EMB], g_Wqklo[(size_t)DQK*EMB];   // [N,K]
__device__ __nv_bfloat16 g_Wvhi[(size_t)EMB*EMB],  g_Wvlo[(size_t)EMB*EMB];
__device__ __nv_bfloat16 g_Wphi[(size_t)EMB*EMB],  g_Wplo[(size_t)EMB*EMB];

// ======================= PTX helpers (arch-portable, sm_80+) =======================
__device__ __forceinline__ uint32_t smem_u32(const void* p) {
    uint32_t a;
    asm("{ .reg .u64 t; cvta.to.shared.u64 t, %1; cvt.u32.u64 %0, t; }" : "=r"(a) : "l"(p));
    return a;
}
#define CP_ASYNC16(saddr, gptr) \
    asm volatile("cp.async.cg.shared.global [%0], [%1], 16;" :: "r"(saddr), "l"(gptr) : "memory")
#define CP_COMMIT() asm volatile("cp.async.commit_group;" ::: "memory")
#define CP_WAIT1()  asm volatile("cp.async.wait_group 1;" ::: "memory")
#define CP_WAIT0()  asm volatile("cp.async.wait_group 0;" ::: "memory")
#define LDMATRIX_X4(r0, r1, r2, r3, addr) \
    asm volatile("ldmatrix.sync.aligned.m8n8.x4.shared.b16 {%0,%1,%2,%3}, [%4];" \
        : "=r"(r0), "=r"(r1), "=r"(r2), "=r"(r3) : "r"(addr))
#define MMA16816(d, a0, a1, a2, a3, b0, b1) \
    asm volatile("mma.sync.aligned.m16n8k16.row.col.f32.bf16.bf16.f32 " \
        "{%0,%1,%2,%3}, {%4,%5,%6,%7}, {%8,%9}, {%0,%1,%2,%3};" \
        : "+f"((d)[0]), "+f"((d)[1]), "+f"((d)[2]), "+f"((d)[3]) \
        : "r"(a0), "r"(a1), "r"(a2), "r"(a3), "r"(b0), "r"(b1))

// ======================= conversion kernels =======================
__global__ __launch_bounds__(256) void convert_split(
    const float* __restrict__ src, __nv_bfloat16* __restrict__ hi,
    __nv_bfloat16* __restrict__ lo, int n)
{
    int i = blockIdx.x * 256 + threadIdx.x;
    if (i < n) {
        float v = src[i];
        __nv_bfloat16 h = __float2bfloat16(v);
        hi[i] = h;
        lo[i] = __float2bfloat16(v - __bfloat162float(h));
    }
}

// W [K][N] fp32 -> Wt hi/lo [N][K] bf16
__global__ __launch_bounds__(256) void transpose_split(
    const float* __restrict__ W, __nv_bfloat16* __restrict__ thi,
    __nv_bfloat16* __restrict__ tlo, int K, int N)
{
    __shared__ float t[32][33];
    int k0 = blockIdx.y * 32, n0 = blockIdx.x * 32;
    int tx = threadIdx.x & 31, ty = threadIdx.x >> 5;   // 32x8
    for (int i = ty; i < 32; i += 8)
        t[i][tx] = W[(size_t)(k0 + i) * N + n0 + tx];
    __syncthreads();
    for (int i = ty; i < 32; i += 8) {
        float v = t[tx][i];
        __nv_bfloat16 h = __float2bfloat16(v);
        size_t o = (size_t)(n0 + i) * K + k0 + tx;
        thi[o] = h;
        tlo[o] = __float2bfloat16(v - __bfloat162float(h));
    }
}

// ======================= mma.sync split-bf16 GEMM =======================
// C[M x N] = Ahi@Bt^T_hi + Ahi@Bt^T_lo + Alo@Bt^T_hi + bias,  K=768 fixed.
// A: [M,768] bf16 row-major.  Bt: [N,768] bf16 row-major.
// CTA 128x128, 8 warps (4m x 2n), warp tile 32x64. K-chunk 32, 72 iterations.
// smem tiles: 128 rows x 64B data, padded to 80B row stride (ldmatrix conflict-free).
#define GROW 80
#define GTILE (128 * GROW)

__device__ __forceinline__ void gemm_load_tile(
    uint32_t sA, uint32_t sB,
    const __nv_bfloat16* __restrict__ Ap, const __nv_bfloat16* __restrict__ Bp,
    int m0, int n0, int kk, int tid)
{
    #pragma unroll
    for (int j = 0; j < 2; j++) {
        int idx = tid + j * 256;          // 512 16B chunks per tile
        int row = idx >> 2, c = idx & 3;
        const char* ga = (const char*)(Ap + (size_t)(m0 + row) * 768 + kk) + c * 16;
        CP_ASYNC16(sA + row * GROW + c * 16, ga);
        const char* gb = (const char*)(Bp + (size_t)(n0 + row) * 768 + kk) + c * 16;
        CP_ASYNC16(sB + row * GROW + c * 16, gb);
    }
}

__global__ __launch_bounds__(256) void gemm_mma(
    const __nv_bfloat16* __restrict__ Ahi, const __nv_bfloat16* __restrict__ Alo,
    const __nv_bfloat16* __restrict__ Bhi, const __nv_bfloat16* __restrict__ Blo,
    const float* __restrict__ bias, float* __restrict__ C, int N)
{
    __shared__ __align__(16) char smem[2][2][GTILE];   // [buf][A/B]

    int tid = threadIdx.x;
    int lane = tid & 31, wid = tid >> 5;
    int wm = wid & 3, wn = wid >> 2;                   // 4 x 2 warp grid
    int m0 = blockIdx.y * 128, n0 = blockIdx.x * 128;

    uint32_t sA[2], sB[2];
    sA[0] = smem_u32(smem[0][0]); sB[0] = smem_u32(smem[0][1]);
    sA[1] = smem_u32(smem[1][0]); sB[1] = smem_u32(smem[1][1]);

    float acc[2][8][4] = {};

    // iter i in [0,72): part = i/24, kk = (i%24)*32
    gemm_load_tile(sA[0], sB[0], Ahi, Bhi, m0, n0, 0, tid);
    CP_COMMIT();

    for (int i = 0; i < 72; i++) {
        int cur = i & 1;
        if (i < 71) {
            int ni = i + 1;
            int part = ni / 24, kk = (ni % 24) * 32;
            const __nv_bfloat16* Ap = (part < 2) ? Ahi : Alo;
            const __nv_bfloat16* Bp = (part == 1) ? Blo : Bhi;
            gemm_load_tile(sA[cur ^ 1], sB[cur ^ 1], Ap, Bp, m0, n0, kk, tid);
            CP_COMMIT();
            CP_WAIT1();
        } else {
            CP_WAIT0();
        }
        __syncthreads();

        #pragma unroll
        for (int ks = 0; ks < 2; ks++) {
            uint32_t a[2][4];
            #pragma unroll
            for (int mf = 0; mf < 2; mf++) {
                uint32_t addr = sA[cur] + (wm * 32 + mf * 16 + (lane & 15)) * GROW
                              + ks * 32 + ((lane >> 4) << 4);
                LDMATRIX_X4(a[mf][0], a[mf][1], a[mf][2], a[mf][3], addr);
            }
            uint32_t bfr[4][4];
            #pragma unroll
            for (int bp = 0; bp < 4; bp++) {
                uint32_t addr = sB[cur] + (wn * 64 + bp * 16 + (lane & 15)) * GROW
                              + ks * 32 + ((lane >> 4) << 4);
                LDMATRIX_X4(bfr[bp][0], bfr[bp][1], bfr[bp][2], bfr[bp][3], addr);
            }
            #pragma unroll
            for (int mf = 0; mf < 2; mf++)
                #pragma unroll
                for (int nf = 0; nf < 8; nf++) {
                    int bp = nf >> 1, o = nf & 1;
                    MMA16816(acc[mf][nf], a[mf][0], a[mf][1], a[mf][2], a[mf][3],
                             bfr[bp][o], bfr[bp][2 + o]);
                }
        }
        __syncthreads();
    }

    // epilogue: direct float2 stores with bias
    #pragma unroll
    for (int mf = 0; mf < 2; mf++) {
        int r = m0 + wm * 32 + mf * 16 + (lane >> 2);
        #pragma unroll
        for (int nf = 0; nf < 8; nf++) {
            int c = n0 + wn * 64 + nf * 8 + ((lane & 3) << 1);
            float2 bv = *(const float2*)(bias + c);
            float2 v0 = make_float2(acc[mf][nf][0] + bv.x, acc[mf][nf][1] + bv.y);
            float2 v1 = make_float2(acc[mf][nf][2] + bv.x, acc[mf][nf][3] + bv.y);
            *(float2*)(C + (size_t)r * N + c) = v0;
            *(float2*)(C + (size_t)(r + 8) * N + c) = v1;
        }
    }
}

// ======================= scatter: tmp -> Q,K,V [B,H,N,64] =======================
__global__ __launch_bounds__(256) void scatter_qkv()
{
    int idx = blockIdx.x * 256 + threadIdx.x;
    if (idx >= BATCH * HEADS * SEQ * HDIM) return;
    int dd = idx & 63;
    int t  = idx >> 6;
    int n  = t & (SEQ - 1);
    t >>= 10;
    int h  = t % HEADS;
    int b  = t / HEADS;

    size_t row = (size_t)(b * SEQ + n);
    float q = g_tmp_qk[row * DQK + h * 128 + dd * 2 + 0];
    float k = g_tmp_qk[row * DQK + h * 128 + dd * 2 + 1];
    float v = g_tmp_v [row * EMB + h * HDIM + dd];
    g_Q[idx] = q;
    g_K[idx] = k;
    g_V[idx] = v;
}

// ======================= flash-style attention (SIMT) =======================
#define AQ 16
#define AT 64

__global__ __launch_bounds__(256) void attention_kernel()
{
    __shared__ float Qs[AQ][65];
    __shared__ float Ks[AT][65];
    __shared__ float Vs[AT][65];

    int b = blockIdx.z, h = blockIdx.y;
    int q0 = blockIdx.x * AQ;
    int tid = threadIdx.x;
    int warp = tid >> 5, lane = tid & 31;
    const float scale = 0.125f;

    const float* Qb = g_Q + ((size_t)(b * HEADS + h) * SEQ + q0) * HDIM;
    const float* Kb = g_K + ((size_t)(b * HEADS + h) * SEQ) * HDIM;
    const float* Vb = g_V + ((size_t)(b * HEADS + h) * SEQ) * HDIM;

    for (int i = tid; i < AQ * HDIM; i += 256) {
        int r = i >> 6, c = i & 63;
        Qs[r][c] = Qb[r * HDIM + c] * scale;
    }

    int r0 = warp * 2, r1 = warp * 2 + 1;
    int c0 = lane, c1 = lane + 32;

    float m0 = -1e30f, m1 = -1e30f;
    float l0 = 0.f, l1 = 0.f;
    float acc00 = 0.f, acc01 = 0.f, acc10 = 0.f, acc11 = 0.f;

    for (int t = 0; t < SEQ; t += AT) {
        __syncthreads();
        for (int i = tid; i < AT * HDIM; i += 256) {
            int r = i >> 6, c = i & 63;
            Ks[r][c] = Kb[(size_t)(t + r) * HDIM + c];
            Vs[r][c] = Vb[(size_t)(t + r) * HDIM + c];
        }
        __syncthreads();

        float s00 = 0.f, s01 = 0.f, s10 = 0.f, s11 = 0.f;
        #pragma unroll
        for (int d = 0; d < HDIM; d++) {
            float qa = Qs[r0][d], qb = Qs[r1][d];
            float ka = Ks[c0][d], kb = Ks[c1][d];
            s00 += qa * ka; s01 += qa * kb;
            s10 += qb * ka; s11 += qb * kb;
        }

        float t0 = fmaxf(s00, s01), t1 = fmaxf(s10, s11);
        #pragma unroll
        for (int o = 16; o; o >>= 1) {
            t0 = fmaxf(t0, __shfl_xor_sync(0xffffffffu, t0, o));
            t1 = fmaxf(t1, __shfl_xor_sync(0xffffffffu, t1, o));
        }
        float nm0 = fmaxf(m0, t0), nm1 = fmaxf(m1, t1);
        float p00 = __expf(s00 - nm0), p01 = __expf(s01 - nm0);
        float p10 = __expf(s10 - nm1), p11 = __expf(s11 - nm1);
        float corr0 = __expf(m0 - nm0), corr1 = __expf(m1 - nm1);
        m0 = nm0; m1 = nm1;

        float ps0 = p00 + p01, ps1 = p10 + p11;
        #pragma unroll
        for (int o = 16; o; o >>= 1) {
            ps0 += __shfl_xor_sync(0xffffffffu, ps0, o);
            ps1 += __shfl_xor_sync(0xffffffffu, ps1, o);
        }
        l0 = l0 * corr0 + ps0;
        l1 = l1 * corr1 + ps1;
        acc00 *= corr0; acc01 *= corr0;
        acc10 *= corr1; acc11 *= corr1;

        #pragma unroll
        for (int kk = 0; kk < 32; kk++) {
            float pa = __shfl_sync(0xffffffffu, p00, kk);
            float pb = __shfl_sync(0xffffffffu, p10, kk);
            float va = Vs[kk][c0], vb = Vs[kk][c1];
            acc00 += pa * va; acc01 += pa * vb;
            acc10 += pb * va; acc11 += pb * vb;
        }
        #pragma unroll
        for (int kk = 0; kk < 32; kk++) {
            float pa = __shfl_sync(0xffffffffu, p01, kk);
            float pb = __shfl_sync(0xffffffffu, p11, kk);
            float va = Vs[32 + kk][c0], vb = Vs[32 + kk][c1];
            acc00 += pa * va; acc01 += pa * vb;
            acc10 += pb * va; acc11 += pb * vb;
        }
    }

    float inv0 = 1.f / l0, inv1 = 1.f / l1;
    int n0 = q0 + r0, n1 = q0 + r1;
    float* Ob = g_O + (size_t)b * SEQ * EMB + h * HDIM;
    Ob[(size_t)n0 * EMB + lane]      = acc00 * inv0;
    Ob[(size_t)n0 * EMB + lane + 32] = acc01 * inv0;
    Ob[(size_t)n1 * EMB + lane]      = acc10 * inv1;
    Ob[(size_t)n1 * EMB + lane + 32] = acc11 * inv1;
}

// ======================= launch =======================
extern "C" void kernel_launch(void* const* d_in, const int* in_sizes, int n_in,
                              void* d_out, int out_size)
{
    const float* x      = (const float*)d_in[0];
    const float* W_qk   = (const float*)d_in[1];
    const float* b_qk   = (const float*)d_in[2];
    const float* W_v    = (const float*)d_in[3];
    const float* b_v    = (const float*)d_in[4];
    const float* W_proj = (const float*)d_in[5];
    const float* b_proj = (const float*)d_in[6];
    float* out = (float*)d_out;

    float *tqk, *tv, *O;
    __nv_bfloat16 *xhi, *xlo, *Ohi, *Olo;
    __nv_bfloat16 *wqh, *wql, *wvh, *wvl, *wph, *wpl;
    cudaGetSymbolAddress((void**)&tqk, g_tmp_qk);
    cudaGetSymbolAddress((void**)&tv,  g_tmp_v);
    cudaGetSymbolAddress((void**)&O,   g_O);
    cudaGetSymbolAddress((void**)&xhi, g_xhi);
    cudaGetSymbolAddress((void**)&xlo, g_xlo);
    cudaGetSymbolAddress((void**)&Ohi, g_Ohi);
    cudaGetSymbolAddress((void**)&Olo, g_Olo);
    cudaGetSymbolAddress((void**)&wqh, g_Wqkhi);
    cudaGetSymbolAddress((void**)&wql, g_Wqklo);
    cudaGetSymbolAddress((void**)&wvh, g_Wvhi);
    cudaGetSymbolAddress((void**)&wvl, g_Wvlo);
    cudaGetSymbolAddress((void**)&wph, g_Wphi);
    cudaGetSymbolAddress((void**)&wpl, g_Wplo);

    // 0) conversions
    {
        int n = MTOT * EMB;
        convert_split<<<(n + 255) / 256, 256>>>(x, xhi, xlo, n);
        transpose_split<<<dim3(DQK / 32, EMB / 32), 256>>>(W_qk, wqh, wql, EMB, DQK);
        transpose_split<<<dim3(EMB / 32, EMB / 32), 256>>>(W_v, wvh, wvl, EMB, EMB);
        transpose_split<<<dim3(EMB / 32, EMB / 32), 256>>>(W_proj, wph, wpl, EMB, EMB);
    }

    // 1) projections (tensor cores via mma.sync)
    gemm_mma<<<dim3(DQK / 128, MTOT / 128), 256>>>(xhi, xlo, wqh, wql, b_qk, tqk, DQK);
    gemm_mma<<<dim3(EMB / 128, MTOT / 128), 256>>>(xhi, xlo, wvh, wvl, b_v, tv, EMB);

    // 2) scatter
    {
        int total = BATCH * HEADS * SEQ * HDIM;
        scatter_qkv<<<(total + 255) / 256, 256>>>();
    }

    // 3) attention
    attention_kernel<<<dim3(SEQ / AQ, HEADS, BATCH), 256>>>();

    // 4) output projection
    {
        int n = MTOT * EMB;
        convert_split<<<(n + 255) / 256, 256>>>(O, Ohi, Olo, n);
        gemm_mma<<<dim3(EMB / 128, MTOT / 128), 256>>>(Ohi, Olo, wph, wpl, b_proj, out, EMB);
    }
}

// round 5
// speedup vs baseline: 3.8498x; 2.6197x over previous
#include <cuda_runtime.h>
#include <cuda_bf16.h>
#include <cstdint>
#include <math.h>

// Problem constants
#define BATCH 16
#define SEQ   1024
#define EMB   768
#define HEADS 12
#define HDIM  64
#define DQK   1536
#define MTOT  (BATCH*SEQ) // 16384

// ======================= scratch =======================
__device__ float g_tmp_qk[(size_t)MTOT * DQK];
__device__ float g_tmp_v [(size_t)MTOT * EMB];
__device__ __nv_bfloat16 g_xhi[(size_t)MTOT*EMB], g_xlo[(size_t)MTOT*EMB];
__device__ __nv_bfloat16 g_Ohi[(size_t)MTOT*EMB], g_Olo[(size_t)MTOT*EMB];
__device__ __nv_bfloat16 g_Wqkhi[(size_t)DQK*EMB], g_Wqklo[(size_t)DQK*EMB];   // [N,K]
__device__ __nv_bfloat16 g_Wvhi[(size_t)EMB*EMB],  g_Wvlo[(size_t)EMB*EMB];
__device__ __nv_bfloat16 g_Wphi[(size_t)EMB*EMB],  g_Wplo[(size_t)EMB*EMB];
// bf16 hi/lo Q,K,V in [B,H,N,64]
#define QKV_ELEMS ((size_t)BATCH*HEADS*SEQ*HDIM)
__device__ __nv_bfloat16 g_Qhi[QKV_ELEMS], g_Qlo[QKV_ELEMS];
__device__ __nv_bfloat16 g_Khi[QKV_ELEMS], g_Klo[QKV_ELEMS];
__device__ __nv_bfloat16 g_Vhi[QKV_ELEMS], g_Vlo[QKV_ELEMS];

// ======================= PTX helpers (arch-portable, sm_80+) =======================
__device__ __forceinline__ uint32_t smem_u32(const void* p) {
    uint32_t a;
    asm("{ .reg .u64 t; cvta.to.shared.u64 t, %1; cvt.u32.u64 %0, t; }" : "=r"(a) : "l"(p));
    return a;
}
#define CP_ASYNC16(saddr, gptr) \
    asm volatile("cp.async.cg.shared.global [%0], [%1], 16;" :: "r"(saddr), "l"(gptr) : "memory")
#define CP_COMMIT() asm volatile("cp.async.commit_group;" ::: "memory")
#define CP_WAIT1()  asm volatile("cp.async.wait_group 1;" ::: "memory")
#define CP_WAIT0()  asm volatile("cp.async.wait_group 0;" ::: "memory")
#define LDMATRIX_X4(r0, r1, r2, r3, addr) \
    asm volatile("ldmatrix.sync.aligned.m8n8.x4.shared.b16 {%0,%1,%2,%3}, [%4];" \
        : "=r"(r0), "=r"(r1), "=r"(r2), "=r"(r3) : "r"(addr))
#define LDMATRIX_X4_T(r0, r1, r2, r3, addr) \
    asm volatile("ldmatrix.sync.aligned.m8n8.x4.trans.shared.b16 {%0,%1,%2,%3}, [%4];" \
        : "=r"(r0), "=r"(r1), "=r"(r2), "=r"(r3) : "r"(addr))
#define MMA16816(d, a0, a1, a2, a3, b0, b1) \
    asm volatile("mma.sync.aligned.m16n8k16.row.col.f32.bf16.bf16.f32 " \
        "{%0,%1,%2,%3}, {%4,%5,%6,%7}, {%8,%9}, {%0,%1,%2,%3};" \
        : "+f"((d)[0]), "+f"((d)[1]), "+f"((d)[2]), "+f"((d)[3]) \
        : "r"(a0), "r"(a1), "r"(a2), "r"(a3), "r"(b0), "r"(b1))

__device__ __forceinline__ float fast_exp2(float x) {
    float y;
    asm("ex2.approx.ftz.f32 %0, %1;" : "=f"(y) : "f"(x));
    return y;
}
// pack (even, odd) floats to bf16x2: even in low half
__device__ __forceinline__ uint32_t pack_bf16x2(__nv_bfloat16 e, __nv_bfloat16 o) {
    __nv_bfloat162 t = __halves2bfloat162(e, o);
    return *(uint32_t*)&t;
}

// ======================= conversion kernels =======================
__global__ __launch_bounds__(256) void convert_split(
    const float* __restrict__ src, __nv_bfloat16* __restrict__ hi,
    __nv_bfloat16* __restrict__ lo, int n)
{
    int i = blockIdx.x * 256 + threadIdx.x;
    if (i < n) {
        float v = src[i];
        __nv_bfloat16 h = __float2bfloat16(v);
        hi[i] = h;
        lo[i] = __float2bfloat16(v - __bfloat162float(h));
    }
}

// W [K][N] fp32 -> Wt hi/lo [N][K] bf16
__global__ __launch_bounds__(256) void transpose_split(
    const float* __restrict__ W, __nv_bfloat16* __restrict__ thi,
    __nv_bfloat16* __restrict__ tlo, int K, int N)
{
    __shared__ float t[32][33];
    int k0 = blockIdx.y * 32, n0 = blockIdx.x * 32;
    int tx = threadIdx.x & 31, ty = threadIdx.x >> 5;   // 32x8
    for (int i = ty; i < 32; i += 8)
        t[i][tx] = W[(size_t)(k0 + i) * N + n0 + tx];
    __syncthreads();
    for (int i = ty; i < 32; i += 8) {
        float v = t[tx][i];
        __nv_bfloat16 h = __float2bfloat16(v);
        size_t o = (size_t)(n0 + i) * K + k0 + tx;
        thi[o] = h;
        tlo[o] = __float2bfloat16(v - __bfloat162float(h));
    }
}

// ======================= mma.sync split-bf16 GEMM =======================
#define GROW 80
#define GTILE (128 * GROW)

__device__ __forceinline__ void gemm_load_tile(
    uint32_t sA, uint32_t sB,
    const __nv_bfloat16* __restrict__ Ap, const __nv_bfloat16* __restrict__ Bp,
    int m0, int n0, int kk, int tid)
{
    #pragma unroll
    for (int j = 0; j < 2; j++) {
        int idx = tid + j * 256;
        int row = idx >> 2, c = idx & 3;
        const char* ga = (const char*)(Ap + (size_t)(m0 + row) * 768 + kk) + c * 16;
        CP_ASYNC16(sA + row * GROW + c * 16, ga);
        const char* gb = (const char*)(Bp + (size_t)(n0 + row) * 768 + kk) + c * 16;
        CP_ASYNC16(sB + row * GROW + c * 16, gb);
    }
}

__global__ __launch_bounds__(256) void gemm_mma(
    const __nv_bfloat16* __restrict__ Ahi, const __nv_bfloat16* __restrict__ Alo,
    const __nv_bfloat16* __restrict__ Bhi, const __nv_bfloat16* __restrict__ Blo,
    const float* __restrict__ bias, float* __restrict__ C, int N)
{
    __shared__ __align__(16) char smem[2][2][GTILE];

    int tid = threadIdx.x;
    int lane = tid & 31, wid = tid >> 5;
    int wm = wid & 3, wn = wid >> 2;
    int m0 = blockIdx.y * 128, n0 = blockIdx.x * 128;

    uint32_t sA[2], sB[2];
    sA[0] = smem_u32(smem[0][0]); sB[0] = smem_u32(smem[0][1]);
    sA[1] = smem_u32(smem[1][0]); sB[1] = smem_u32(smem[1][1]);

    float acc[2][8][4] = {};

    gemm_load_tile(sA[0], sB[0], Ahi, Bhi, m0, n0, 0, tid);
    CP_COMMIT();

    for (int i = 0; i < 72; i++) {
        int cur = i & 1;
        if (i < 71) {
            int ni = i + 1;
            int part = ni / 24, kk = (ni % 24) * 32;
            const __nv_bfloat16* Ap = (part < 2) ? Ahi : Alo;
            const __nv_bfloat16* Bp = (part == 1) ? Blo : Bhi;
            gemm_load_tile(sA[cur ^ 1], sB[cur ^ 1], Ap, Bp, m0, n0, kk, tid);
            CP_COMMIT();
            CP_WAIT1();
        } else {
            CP_WAIT0();
        }
        __syncthreads();

        #pragma unroll
        for (int ks = 0; ks < 2; ks++) {
            uint32_t a[2][4];
            #pragma unroll
            for (int mf = 0; mf < 2; mf++) {
                uint32_t addr = sA[cur] + (wm * 32 + mf * 16 + (lane & 15)) * GROW
                              + ks * 32 + ((lane >> 4) << 4);
                LDMATRIX_X4(a[mf][0], a[mf][1], a[mf][2], a[mf][3], addr);
            }
            uint32_t bfr[4][4];
            #pragma unroll
            for (int bp = 0; bp < 4; bp++) {
                uint32_t addr = sB[cur] + (wn * 64 + bp * 16 + (lane & 15)) * GROW
                              + ks * 32 + ((lane >> 4) << 4);
                LDMATRIX_X4(bfr[bp][0], bfr[bp][1], bfr[bp][2], bfr[bp][3], addr);
            }
            #pragma unroll
            for (int mf = 0; mf < 2; mf++)
                #pragma unroll
                for (int nf = 0; nf < 8; nf++) {
                    int bp = nf >> 1, o = nf & 1;
                    MMA16816(acc[mf][nf], a[mf][0], a[mf][1], a[mf][2], a[mf][3],
                             bfr[bp][o], bfr[bp][2 + o]);
                }
        }
        __syncthreads();
    }

    #pragma unroll
    for (int mf = 0; mf < 2; mf++) {
        int r = m0 + wm * 32 + mf * 16 + (lane >> 2);
        #pragma unroll
        for (int nf = 0; nf < 8; nf++) {
            int c = n0 + wn * 64 + nf * 8 + ((lane & 3) << 1);
            float2 bv = *(const float2*)(bias + c);
            float2 v0 = make_float2(acc[mf][nf][0] + bv.x, acc[mf][nf][1] + bv.y);
            float2 v1 = make_float2(acc[mf][nf][2] + bv.x, acc[mf][nf][3] + bv.y);
            *(float2*)(C + (size_t)r * N + c) = v0;
            *(float2*)(C + (size_t)(r + 8) * N + c) = v1;
        }
    }
}

// ======================= scatter+split: tmp -> bf16 hi/lo Q,K,V [B,H,N,64] =======================
// Q pre-scaled by 1/sqrt(64) * log2(e) so softmax uses exp2 directly.
#define QSCALE 0.18033688011112042f
__global__ __launch_bounds__(256) void scatter_split_qkv()
{
    int idx = blockIdx.x * 256 + threadIdx.x;
    if (idx >= (int)QKV_ELEMS) return;
    int dd = idx & 63;
    int t  = idx >> 6;
    int n  = t & (SEQ - 1);
    t >>= 10;
    int h  = t % HEADS;
    int b  = t / HEADS;

    size_t row = (size_t)(b * SEQ + n);
    float q = g_tmp_qk[row * DQK + h * 128 + dd * 2 + 0] * QSCALE;
    float k = g_tmp_qk[row * DQK + h * 128 + dd * 2 + 1];
    float v = g_tmp_v [row * EMB + h * HDIM + dd];

    __nv_bfloat16 qh = __float2bfloat16(q);
    g_Qhi[idx] = qh;
    g_Qlo[idx] = __float2bfloat16(q - __bfloat162float(qh));
    __nv_bfloat16 kh = __float2bfloat16(k);
    g_Khi[idx] = kh;
    g_Klo[idx] = __float2bfloat16(k - __bfloat162float(kh));
    __nv_bfloat16 vh = __float2bfloat16(v);
    g_Vhi[idx] = vh;
    g_Vlo[idx] = __float2bfloat16(v - __bfloat162float(vh));
}

// ======================= tensor-core flash attention =======================
// grid (SEQ/128, HEADS, BATCH), 256 threads (8 warps), warp owns 16 q rows.
// KV tiles of 64 keys, double-buffered cp.async.
// smem rows: 64 bf16 = 128B data padded to 144B stride.
#define AROW 144
#define QSM  (128 * AROW)        // 18432 per Q array
#define KVSM (64 * AROW)         // 9216 per KV array
#define ABUF (4 * KVSM)          // Khi,Klo,Vhi,Vlo per buffer
#define ATT_SMEM (2 * QSM + 2 * ABUF)   // 110592

__device__ __forceinline__ void attn_kv_load(
    uint32_t sKV, const __nv_bfloat16* Kh, const __nv_bfloat16* Kl,
    const __nv_bfloat16* Vh, const __nv_bfloat16* Vl, int t, int tid)
{
    #pragma unroll
    for (int j = 0; j < 8; j++) {
        int id = tid + j * 256;               // 0..2047
        int arr = id >> 9, r = (id >> 3) & 63, c = id & 7;
        const __nv_bfloat16* g = (arr == 0) ? Kh : (arr == 1) ? Kl : (arr == 2) ? Vh : Vl;
        CP_ASYNC16(sKV + arr * KVSM + r * AROW + c * 16,
                   g + (size_t)(t * 64 + r) * 64 + c * 8);
    }
}

__global__ __launch_bounds__(256, 1) void attn_mma()
{
    extern __shared__ __align__(16) char sm[];
    const int tid = threadIdx.x, lane = tid & 31, wid = tid >> 5;
    const int b = blockIdx.z, h = blockIdx.y, q0 = blockIdx.x * 128;
    const size_t head = ((size_t)b * HEADS + h) * SEQ;

    const __nv_bfloat16* Qh_g = g_Qhi + (head + q0) * 64;
    const __nv_bfloat16* Ql_g = g_Qlo + (head + q0) * 64;
    const __nv_bfloat16* Kh_g = g_Khi + head * 64;
    const __nv_bfloat16* Kl_g = g_Klo + head * 64;
    const __nv_bfloat16* Vh_g = g_Vhi + head * 64;
    const __nv_bfloat16* Vl_g = g_Vlo + head * 64;

    uint32_t sQ  = smem_u32(sm);
    uint32_t sKV = sQ + 2 * QSM;

    // stage Q (hi+lo) and KV tiles 0,1
    #pragma unroll
    for (int j = 0; j < 8; j++) {
        int id = tid + j * 256;               // 0..2047
        int arr = id >> 10, r = (id >> 3) & 127, c = id & 7;
        const __nv_bfloat16* g = (arr ? Ql_g : Qh_g) + (size_t)r * 64 + c * 8;
        CP_ASYNC16(sQ + arr * QSM + r * AROW + c * 16, g);
    }
    attn_kv_load(sKV, Kh_g, Kl_g, Vh_g, Vl_g, 0, tid);
    CP_COMMIT();
    attn_kv_load(sKV + ABUF, Kh_g, Kl_g, Vh_g, Vl_g, 1, tid);
    CP_COMMIT();
    CP_WAIT1();
    __syncthreads();

    // Q fragments (held in registers for whole kernel)
    uint32_t qh[4][4], ql[4][4];
    #pragma unroll
    for (int ks = 0; ks < 4; ks++) {
        uint32_t a = sQ + (wid * 16 + (lane & 15)) * AROW + ks * 32 + ((lane >> 4) << 4);
        LDMATRIX_X4(qh[ks][0], qh[ks][1], qh[ks][2], qh[ks][3], a);
        LDMATRIX_X4(ql[ks][0], ql[ks][1], ql[ks][2], ql[ks][3], a + QSM);
    }

    float acc[8][4] = {};
    float mA = -1e30f, mB = -1e30f, lA = 0.f, lB = 0.f;

    for (int t = 0; t < 16; t++) {
        int cur = t & 1;
        if (t < 15) CP_WAIT1(); else CP_WAIT0();
        __syncthreads();

        uint32_t kb = sKV + cur * ABUF;

        // ---- S = Qhi*Khi + Qhi*Klo + Qlo*Khi ----
        float s[8][4] = {};
        #pragma unroll
        for (int ks = 0; ks < 4; ks++) {
            uint32_t kh[4][4], kl[4][4];
            #pragma unroll
            for (int p = 0; p < 4; p++) {
                uint32_t a = kb + (p * 16 + (lane & 15)) * AROW + ks * 32 + ((lane >> 4) << 4);
                LDMATRIX_X4(kh[p][0], kh[p][1], kh[p][2], kh[p][3], a);
                LDMATRIX_X4(kl[p][0], kl[p][1], kl[p][2], kl[p][3], a + KVSM);
            }
            #pragma unroll
            for (int p = 0; p < 4; p++) {
                MMA16816(s[2*p],   qh[ks][0], qh[ks][1], qh[ks][2], qh[ks][3], kh[p][0], kh[p][2]);
                MMA16816(s[2*p+1], qh[ks][0], qh[ks][1], qh[ks][2], qh[ks][3], kh[p][1], kh[p][3]);
                MMA16816(s[2*p],   qh[ks][0], qh[ks][1], qh[ks][2], qh[ks][3], kl[p][0], kl[p][2]);
                MMA16816(s[2*p+1], qh[ks][0], qh[ks][1], qh[ks][2], qh[ks][3], kl[p][1], kl[p][3]);
                MMA16816(s[2*p],   ql[ks][0], ql[ks][1], ql[ks][2], ql[ks][3], kh[p][0], kh[p][2]);
                MMA16816(s[2*p+1], ql[ks][0], ql[ks][1], ql[ks][2], ql[ks][3], kh[p][1], kh[p][3]);
            }
        }

        // ---- online softmax (exp2 domain; scale folded into Q) ----
        float mxA = -1e30f, mxB = -1e30f;
        #pragma unroll
        for (int nb = 0; nb < 8; nb++) {
            mxA = fmaxf(mxA, fmaxf(s[nb][0], s[nb][1]));
            mxB = fmaxf(mxB, fmaxf(s[nb][2], s[nb][3]));
        }
        mxA = fmaxf(mxA, __shfl_xor_sync(0xffffffffu, mxA, 1));
        mxA = fmaxf(mxA, __shfl_xor_sync(0xffffffffu, mxA, 2));
        mxB = fmaxf(mxB, __shfl_xor_sync(0xffffffffu, mxB, 1));
        mxB = fmaxf(mxB, __shfl_xor_sync(0xffffffffu, mxB, 2));
        float mAn = fmaxf(mA, mxA), mBn = fmaxf(mB, mxB);
        float corrA = fast_exp2(mA - mAn), corrB = fast_exp2(mB - mBn);
        mA = mAn; mB = mBn;

        uint32_t phiA[8], ploA[8], phiB[8], ploB[8];
        float sumA = 0.f, sumB = 0.f;
        #pragma unroll
        for (int nb = 0; nb < 8; nb++) {
            float p0 = fast_exp2(s[nb][0] - mAn);
            float p1 = fast_exp2(s[nb][1] - mAn);
            float p2 = fast_exp2(s[nb][2] - mBn);
            float p3 = fast_exp2(s[nb][3] - mBn);
            sumA += p0 + p1; sumB += p2 + p3;
            __nv_bfloat16 h0 = __float2bfloat16(p0), h1 = __float2bfloat16(p1);
            __nv_bfloat16 h2 = __float2bfloat16(p2), h3 = __float2bfloat16(p3);
            phiA[nb] = pack_bf16x2(h0, h1);
            phiB[nb] = pack_bf16x2(h2, h3);
            ploA[nb] = pack_bf16x2(__float2bfloat16(p0 - __bfloat162float(h0)),
                                   __float2bfloat16(p1 - __bfloat162float(h1)));
            ploB[nb] = pack_bf16x2(__float2bfloat16(p2 - __bfloat162float(h2)),
                                   __float2bfloat16(p3 - __bfloat162float(h3)));
        }
        sumA += __shfl_xor_sync(0xffffffffu, sumA, 1);
        sumA += __shfl_xor_sync(0xffffffffu, sumA, 2);
        sumB += __shfl_xor_sync(0xffffffffu, sumB, 1);
        sumB += __shfl_xor_sync(0xffffffffu, sumB, 2);
        lA = lA * corrA + sumA;
        lB = lB * corrB + sumB;
        #pragma unroll
        for (int nb = 0; nb < 8; nb++) {
            acc[nb][0] *= corrA; acc[nb][1] *= corrA;
            acc[nb][2] *= corrB; acc[nb][3] *= corrB;
        }

        // ---- O += Phi*Vhi + Phi*Vlo + Plo*Vhi ----
        uint32_t vb = kb + 2 * KVSM;
        #pragma unroll
        for (int kt = 0; kt < 4; kt++) {     // key chunks of 16
            #pragma unroll
            for (int p = 0; p < 4; p++) {    // hdim nb pairs
                uint32_t vh0, vh1, vh2, vh3, vl0, vl1, vl2, vl3;
                uint32_t a = vb + (kt * 16 + (lane & 15)) * AROW + p * 32 + ((lane >> 4) << 4);
                LDMATRIX_X4_T(vh0, vh1, vh2, vh3, a);
                LDMATRIX_X4_T(vl0, vl1, vl2, vl3, a + KVSM);
                MMA16816(acc[2*p],   phiA[2*kt], phiB[2*kt], phiA[2*kt+1], phiB[2*kt+1], vh0, vh1);
                MMA16816(acc[2*p+1], phiA[2*kt], phiB[2*kt], phiA[2*kt+1], phiB[2*kt+1], vh2, vh3);
                MMA16816(acc[2*p],   phiA[2*kt], phiB[2*kt], phiA[2*kt+1], phiB[2*kt+1], vl0, vl1);
                MMA16816(acc[2*p+1], phiA[2*kt], phiB[2*kt], phiA[2*kt+1], phiB[2*kt+1], vl2, vl3);
                MMA16816(acc[2*p],   ploA[2*kt], ploB[2*kt], ploA[2*kt+1], ploB[2*kt+1], vh0, vh1);
                MMA16816(acc[2*p+1], ploA[2*kt], ploB[2*kt], ploA[2*kt+1], ploB[2*kt+1], vh2, vh3);
            }
        }

        __syncthreads();
        if (t < 14) {
            attn_kv_load(sKV + cur * ABUF, Kh_g, Kl_g, Vh_g, Vl_g, t + 2, tid);
            CP_COMMIT();
        }
    }

    // ---- epilogue: write bf16 hi/lo O directly ----
    float invA = 1.f / lA, invB = 1.f / lB;
    int rA = q0 + wid * 16 + (lane >> 2);
    int rB = rA + 8;
    size_t baseA = ((size_t)b * SEQ + rA) * EMB + h * 64;
    size_t baseB = ((size_t)b * SEQ + rB) * EMB + h * 64;
    #pragma unroll
    for (int nb = 0; nb < 8; nb++) {
        int col = nb * 8 + ((lane & 3) << 1);
        float o0 = acc[nb][0] * invA, o1 = acc[nb][1] * invA;
        float o2 = acc[nb][2] * invB, o3 = acc[nb][3] * invB;
        __nv_bfloat16 h0 = __float2bfloat16(o0), h1 = __float2bfloat16(o1);
        __nv_bfloat16 h2 = __float2bfloat16(o2), h3 = __float2bfloat16(o3);
        *(uint32_t*)(g_Ohi + baseA + col) = pack_bf16x2(h0, h1);
        *(uint32_t*)(g_Ohi + baseB + col) = pack_bf16x2(h2, h3);
        *(uint32_t*)(g_Olo + baseA + col) = pack_bf16x2(
            __float2bfloat16(o0 - __bfloat162float(h0)),
            __float2bfloat16(o1 - __bfloat162float(h1)));
        *(uint32_t*)(g_Olo + baseB + col) = pack_bf16x2(
            __float2bfloat16(o2 - __bfloat162float(h2)),
            __float2bfloat16(o3 - __bfloat162float(h3)));
    }
}

// ======================= launch =======================
extern "C" void kernel_launch(void* const* d_in, const int* in_sizes, int n_in,
                              void* d_out, int out_size)
{
    const float* x      = (const float*)d_in[0];
    const float* W_qk   = (const float*)d_in[1];
    const float* b_qk   = (const float*)d_in[2];
    const float* W_v    = (const float*)d_in[3];
    const float* b_v    = (const float*)d_in[4];
    const float* W_proj = (const float*)d_in[5];
    const float* b_proj = (const float*)d_in[6];
    float* out = (float*)d_out;

    float *tqk, *tv;
    __nv_bfloat16 *xhi, *xlo, *Ohi, *Olo;
    __nv_bfloat16 *wqh, *wql, *wvh, *wvl, *wph, *wpl;
    cudaGetSymbolAddress((void**)&tqk, g_tmp_qk);
    cudaGetSymbolAddress((void**)&tv,  g_tmp_v);
    cudaGetSymbolAddress((void**)&xhi, g_xhi);
    cudaGetSymbolAddress((void**)&xlo, g_xlo);
    cudaGetSymbolAddress((void**)&Ohi, g_Ohi);
    cudaGetSymbolAddress((void**)&Olo, g_Olo);
    cudaGetSymbolAddress((void**)&wqh, g_Wqkhi);
    cudaGetSymbolAddress((void**)&wql, g_Wqklo);
    cudaGetSymbolAddress((void**)&wvh, g_Wvhi);
    cudaGetSymbolAddress((void**)&wvl, g_Wvlo);
    cudaGetSymbolAddress((void**)&wph, g_Wphi);
    cudaGetSymbolAddress((void**)&wpl, g_Wplo);

    cudaFuncSetAttribute(attn_mma, cudaFuncAttributeMaxDynamicSharedMemorySize, ATT_SMEM);

    // 0) conversions
    {
        int n = MTOT * EMB;
        convert_split<<<(n + 255) / 256, 256>>>(x, xhi, xlo, n);
        transpose_split<<<dim3(DQK / 32, EMB / 32), 256>>>(W_qk, wqh, wql, EMB, DQK);
        transpose_split<<<dim3(EMB / 32, EMB / 32), 256>>>(W_v, wvh, wvl, EMB, EMB);
        transpose_split<<<dim3(EMB / 32, EMB / 32), 256>>>(W_proj, wph, wpl, EMB, EMB);
    }

    // 1) projections (tensor cores)
    gemm_mma<<<dim3(DQK / 128, MTOT / 128), 256>>>(xhi, xlo, wqh, wql, b_qk, tqk, DQK);
    gemm_mma<<<dim3(EMB / 128, MTOT / 128), 256>>>(xhi, xlo, wvh, wvl, b_v, tv, EMB);

    // 2) scatter + bf16 split
    {
        int total = (int)QKV_ELEMS;
        scatter_split_qkv<<<(total + 255) / 256, 256>>>();
    }

    // 3) tensor-core flash attention (writes Ohi/Olo directly)
    attn_mma<<<dim3(SEQ / 128, HEADS, BATCH), 256, ATT_SMEM>>>();

    // 4) output projection
    gemm_mma<<<dim3(EMB / 128, MTOT / 128), 256>>>(Ohi, Olo, wph, wpl, b_proj, out, EMB);
}